// round 1
// baseline (speedup 1.0000x reference)
#include <cuda_runtime.h>
#include <math.h>

#define B_   4
#define CIN  256
#define CQ   32
#define D_   24
#define N3   13824   // 24^3
#define M3   1728    // 12^3
#define TK   48      // key chunk

// Scratch (device globals; no allocation)
__device__ float g_f[B_ * N3 * CQ];      // f: [b][n][32]
__device__ float g_graw[B_ * N3 * CQ];   // pre-pool g
__device__ float g_hraw[B_ * N3 * CQ];   // pre-pool h
__device__ float g_gp[B_ * M3 * CQ];     // pooled g: [b][m][32]
__device__ float g_hp[B_ * M3 * CQ];     // pooled h

// ---------------------------------------------------------------------------
// Projection: y[b][n][c'] for 96 outputs (f, graw, hraw) = W @ x[:, n]
// Block: 128 threads = 128 spatial positions; accumulate over C=256 in chunks.
// ---------------------------------------------------------------------------
__global__ __launch_bounds__(128) void proj_kernel(
    const float* __restrict__ x,
    const float* __restrict__ Wf,
    const float* __restrict__ Wg,
    const float* __restrict__ Wh)
{
    __shared__ float xs[32][128];
    __shared__ float wsf[32][32];   // [ci][c'] transposed chunks
    __shared__ float wsg[32][32];
    __shared__ float wsh[32][32];

    const int b   = blockIdx.y;
    const int n0  = blockIdx.x * 128;
    const int tid = threadIdx.x;

    float accF[32], accG[32], accH[32];
#pragma unroll
    for (int i = 0; i < 32; i++) { accF[i] = 0.f; accG[i] = 0.f; accH[i] = 0.f; }

    for (int cc0 = 0; cc0 < CIN; cc0 += 32) {
        __syncthreads();
#pragma unroll
        for (int r = 0; r < 32; r++) {
            xs[r][tid] = x[((size_t)b * CIN + cc0 + r) * N3 + n0 + tid];
        }
        for (int i = tid; i < 1024; i += 128) {
            int ci = i >> 5, cp = i & 31;
            wsf[ci][cp] = Wf[cp * CIN + cc0 + ci];
            wsg[ci][cp] = Wg[cp * CIN + cc0 + ci];
            wsh[ci][cp] = Wh[cp * CIN + cc0 + ci];
        }
        __syncthreads();

#pragma unroll 8
        for (int ci = 0; ci < 32; ci++) {
            float xv = xs[ci][tid];
#pragma unroll
            for (int c4 = 0; c4 < 8; c4++) {
                float4 wf = *(const float4*)&wsf[ci][c4 * 4];
                float4 wg = *(const float4*)&wsg[ci][c4 * 4];
                float4 wh = *(const float4*)&wsh[ci][c4 * 4];
                accF[c4*4+0] = fmaf(xv, wf.x, accF[c4*4+0]);
                accF[c4*4+1] = fmaf(xv, wf.y, accF[c4*4+1]);
                accF[c4*4+2] = fmaf(xv, wf.z, accF[c4*4+2]);
                accF[c4*4+3] = fmaf(xv, wf.w, accF[c4*4+3]);
                accG[c4*4+0] = fmaf(xv, wg.x, accG[c4*4+0]);
                accG[c4*4+1] = fmaf(xv, wg.y, accG[c4*4+1]);
                accG[c4*4+2] = fmaf(xv, wg.z, accG[c4*4+2]);
                accG[c4*4+3] = fmaf(xv, wg.w, accG[c4*4+3]);
                accH[c4*4+0] = fmaf(xv, wh.x, accH[c4*4+0]);
                accH[c4*4+1] = fmaf(xv, wh.y, accH[c4*4+1]);
                accH[c4*4+2] = fmaf(xv, wh.z, accH[c4*4+2]);
                accH[c4*4+3] = fmaf(xv, wh.w, accH[c4*4+3]);
            }
        }
    }

    size_t base = ((size_t)b * N3 + n0 + tid) * CQ;
#pragma unroll
    for (int c4 = 0; c4 < 8; c4++) {
        *(float4*)&g_f[base + c4*4]    = make_float4(accF[c4*4+0], accF[c4*4+1], accF[c4*4+2], accF[c4*4+3]);
        *(float4*)&g_graw[base + c4*4] = make_float4(accG[c4*4+0], accG[c4*4+1], accG[c4*4+2], accG[c4*4+3]);
        *(float4*)&g_hraw[base + c4*4] = make_float4(accH[c4*4+0], accH[c4*4+1], accH[c4*4+2], accH[c4*4+3]);
    }
}

// ---------------------------------------------------------------------------
// 2x2x2 max pool on graw/hraw -> gp/hp. One thread per (b, m, c').
// ---------------------------------------------------------------------------
__global__ void pool_kernel()
{
    int idx = blockIdx.x * 256 + threadIdx.x;
    const int total = B_ * M3 * CQ;
    if (idx >= total) return;
    int c = idx & 31;
    int m = (idx >> 5) % M3;
    int b = idx / (M3 * CQ);
    int md = m / 144, mh = (m / 12) % 12, mw = m % 12;

    float gmax = -INFINITY, hmax = -INFINITY;
#pragma unroll
    for (int dd = 0; dd < 2; dd++)
#pragma unroll
        for (int dh = 0; dh < 2; dh++)
#pragma unroll
            for (int dw = 0; dw < 2; dw++) {
                int n = (2*md + dd) * 576 + (2*mh + dh) * 24 + (2*mw + dw);
                size_t o = ((size_t)b * N3 + n) * CQ + c;
                gmax = fmaxf(gmax, g_graw[o]);
                hmax = fmaxf(hmax, g_hraw[o]);
            }
    size_t po = ((size_t)b * M3 + m) * CQ + c;
    g_gp[po] = gmax;
    g_hp[po] = hmax;
}

// ---------------------------------------------------------------------------
// Attention + Wv epilogue + residual. Block = 128 threads = 128 queries.
// Streams keys in chunks of TK; no-max softmax (scores bounded ~|45| << 88).
// ---------------------------------------------------------------------------
__global__ __launch_bounds__(128) void attn_kernel(
    const float* __restrict__ x,
    const float* __restrict__ Wv,
    const float* __restrict__ gamma_p,
    float* __restrict__ out)
{
    __shared__ float sWv[CIN * CQ];  // 32 KB
    __shared__ float gk[TK][CQ];     // 6 KB
    __shared__ float hk[TK][CQ];     // 6 KB

    const int b   = blockIdx.y;
    const int tid = threadIdx.x;
    const int q   = blockIdx.x * 128 + tid;

    for (int i = tid; i < CIN * CQ; i += 128) sWv[i] = Wv[i];

    float fq[32];
    {
        size_t fb = ((size_t)b * N3 + q) * CQ;
#pragma unroll
        for (int c4 = 0; c4 < 8; c4++) {
            float4 v = *(const float4*)&g_f[fb + c4*4];
            fq[c4*4+0] = v.x; fq[c4*4+1] = v.y; fq[c4*4+2] = v.z; fq[c4*4+3] = v.w;
        }
    }

    float acc[32];
#pragma unroll
    for (int i = 0; i < 32; i++) acc[i] = 0.f;
    float l = 0.f;

    for (int k0 = 0; k0 < M3; k0 += TK) {
        __syncthreads();
        {
            const float4* gsrc = (const float4*)(g_gp + ((size_t)b * M3 + k0) * CQ);
            const float4* hsrc = (const float4*)(g_hp + ((size_t)b * M3 + k0) * CQ);
            float4* gdst = (float4*)&gk[0][0];
            float4* hdst = (float4*)&hk[0][0];
#pragma unroll
            for (int i = 0; i < (TK * CQ / 4) / 128; i++) {
                gdst[tid + i * 128] = gsrc[tid + i * 128];
                hdst[tid + i * 128] = hsrc[tid + i * 128];
            }
        }
        __syncthreads();

#pragma unroll 4
        for (int j = 0; j < TK; j++) {
            float s = 0.f;
#pragma unroll
            for (int c4 = 0; c4 < 8; c4++) {
                float4 gv = *(const float4*)&gk[j][c4 * 4];
                s = fmaf(fq[c4*4+0], gv.x, s);
                s = fmaf(fq[c4*4+1], gv.y, s);
                s = fmaf(fq[c4*4+2], gv.z, s);
                s = fmaf(fq[c4*4+3], gv.w, s);
            }
            float p = __expf(s);
            l += p;
#pragma unroll
            for (int c4 = 0; c4 < 8; c4++) {
                float4 hv = *(const float4*)&hk[j][c4 * 4];
                acc[c4*4+0] = fmaf(p, hv.x, acc[c4*4+0]);
                acc[c4*4+1] = fmaf(p, hv.y, acc[c4*4+1]);
                acc[c4*4+2] = fmaf(p, hv.z, acc[c4*4+2]);
                acc[c4*4+3] = fmaf(p, hv.w, acc[c4*4+3]);
            }
        }
    }

    float inv = 1.0f / l;
#pragma unroll
    for (int i = 0; i < 32; i++) acc[i] *= inv;

    const float gma = *gamma_p;
    size_t xb = (size_t)b * CIN * N3 + q;
#pragma unroll 4
    for (int cc = 0; cc < CIN; cc++) {
        float s = 0.f;
#pragma unroll
        for (int c4 = 0; c4 < 8; c4++) {
            float4 w = *(const float4*)&sWv[cc * CQ + c4 * 4];
            s = fmaf(acc[c4*4+0], w.x, s);
            s = fmaf(acc[c4*4+1], w.y, s);
            s = fmaf(acc[c4*4+2], w.z, s);
            s = fmaf(acc[c4*4+3], w.w, s);
        }
        size_t o = xb + (size_t)cc * N3;
        out[o] = fmaf(gma, s, x[o]);
    }
}

// ---------------------------------------------------------------------------
extern "C" void kernel_launch(void* const* d_in, const int* in_sizes, int n_in,
                              void* d_out, int out_size)
{
    const float* x     = (const float*)d_in[0];
    const float* Wf    = (const float*)d_in[1];
    const float* Wg    = (const float*)d_in[2];
    const float* Wh    = (const float*)d_in[3];
    const float* Wv    = (const float*)d_in[4];
    const float* gamma = (const float*)d_in[5];
    float* out = (float*)d_out;

    dim3 pgrid(N3 / 128, B_);
    proj_kernel<<<pgrid, 128>>>(x, Wf, Wg, Wh);

    int ptotal = B_ * M3 * CQ;
    pool_kernel<<<(ptotal + 255) / 256, 256>>>();

    dim3 agrid(N3 / 128, B_);
    attn_kernel<<<agrid, 128>>>(x, Wv, gamma, out);
}

// round 2
// speedup vs baseline: 1.1511x; 1.1511x over previous
#include <cuda_runtime.h>
#include <math.h>

#define B_   4
#define CIN  256
#define CQ   32
#define N3   13824   // 24^3
#define M3   1728    // 12^3
#define TK   48      // key chunk

using u64 = unsigned long long;

// ---- packed f32x2 helpers (sm_103a FFMA2 path) ----
__device__ __forceinline__ u64 pack2(float lo, float hi) {
    u64 r; asm("mov.b64 %0, {%1, %2};" : "=l"(r) : "f"(lo), "f"(hi)); return r;
}
__device__ __forceinline__ void unpack2(u64 v, float& lo, float& hi) {
    asm("mov.b64 {%0, %1}, %2;" : "=f"(lo), "=f"(hi) : "l"(v));
}
__device__ __forceinline__ u64 fma2(u64 a, u64 b, u64 c) {
    u64 d; asm("fma.rn.f32x2 %0, %1, %2, %3;" : "=l"(d) : "l"(a), "l"(b), "l"(c));
    return d;
}
__device__ __forceinline__ u64 mul2(u64 a, u64 b) {
    u64 d; asm("mul.rn.f32x2 %0, %1, %2;" : "=l"(d) : "l"(a), "l"(b));
    return d;
}

// Scratch (device globals; no allocation)
__device__ float g_f[B_ * N3 * CQ];      // f: [b][n][32]
__device__ float g_graw[B_ * N3 * CQ];   // pre-pool g
__device__ float g_hraw[B_ * N3 * CQ];   // pre-pool h
__device__ float g_gp[B_ * M3 * CQ];     // pooled g: [b][m][32]
__device__ float g_hp[B_ * M3 * CQ];     // pooled h

// ---------------------------------------------------------------------------
// Projection: one W matrix per gridDim.z (0=f, 1=g, 2=h).
// Block: 128 threads, 256 positions (2 per thread). FFMA2 inner loop.
// ---------------------------------------------------------------------------
__global__ __launch_bounds__(128) void proj_kernel(
    const float* __restrict__ x,
    const float* __restrict__ Wf,
    const float* __restrict__ Wg,
    const float* __restrict__ Wh)
{
    __shared__ float xs[32][256];   // 32 KB
    __shared__ float ws[32][32];    // 4 KB  [ci][c'] transposed chunk

    const int b   = blockIdx.y;
    const int z   = blockIdx.z;
    const int n0  = blockIdx.x * 256;
    const int tid = threadIdx.x;

    const float* W = (z == 0) ? Wf : (z == 1) ? Wg : Wh;
    float* dst = (z == 0) ? g_f : (z == 1) ? g_graw : g_hraw;

    u64 acc0[16], acc1[16];
#pragma unroll
    for (int i = 0; i < 16; i++) { acc0[i] = 0ull; acc1[i] = 0ull; }

    for (int cc0 = 0; cc0 < CIN; cc0 += 32) {
        __syncthreads();
        // load x chunk: 32 rows x 256 cols
        {
            const float4* xsrc = (const float4*)(x + ((size_t)b * CIN + cc0) * N3 + n0);
            // row stride in float4: N3/4
            float4* xdst = (float4*)&xs[0][0];
#pragma unroll
            for (int i = 0; i < 16; i++) {
                int idx = tid + i * 128;          // 0..2047 float4s
                int row = idx >> 6;               // /64 float4s per row
                int c4  = idx & 63;
                xdst[idx] = xsrc[(size_t)row * (N3 / 4) + c4];
            }
        }
        // load weight chunk transposed: ws[ci][cp] = W[cp*CIN + cc0+ci]
#pragma unroll
        for (int i = 0; i < 8; i++) {
            int idx = tid + i * 128;
            int ci = idx >> 5, cp = idx & 31;
            ws[ci][cp] = W[cp * CIN + cc0 + ci];
        }
        __syncthreads();

#pragma unroll
        for (int ci = 0; ci < 32; ci++) {
            float x0 = xs[ci][tid];
            float x1 = xs[ci][tid + 128];
            u64 xv0 = pack2(x0, x0);
            u64 xv1 = pack2(x1, x1);
            const ulonglong2* wp = (const ulonglong2*)&ws[ci][0];
#pragma unroll
            for (int c = 0; c < 8; c++) {
                ulonglong2 w = wp[c];
                acc0[2*c + 0] = fma2(xv0, w.x, acc0[2*c + 0]);
                acc0[2*c + 1] = fma2(xv0, w.y, acc0[2*c + 1]);
                acc1[2*c + 0] = fma2(xv1, w.x, acc1[2*c + 0]);
                acc1[2*c + 1] = fma2(xv1, w.y, acc1[2*c + 1]);
            }
        }
    }

    // store: dst[b][n][32] with n = n0+tid and n0+128+tid (bitwise pair = float pair)
    {
        ulonglong2* d0 = (ulonglong2*)(dst + ((size_t)b * N3 + n0 + tid) * CQ);
        ulonglong2* d1 = (ulonglong2*)(dst + ((size_t)b * N3 + n0 + 128 + tid) * CQ);
#pragma unroll
        for (int c = 0; c < 8; c++) {
            d0[c] = make_ulonglong2(acc0[2*c], acc0[2*c + 1]);
            d1[c] = make_ulonglong2(acc1[2*c], acc1[2*c + 1]);
        }
    }
}

// ---------------------------------------------------------------------------
// 2x2x2 max pool on graw/hraw -> gp/hp. One thread per (b, m, c').
// ---------------------------------------------------------------------------
__global__ void pool_kernel()
{
    int idx = blockIdx.x * 256 + threadIdx.x;
    const int total = B_ * M3 * CQ;
    if (idx >= total) return;
    int c = idx & 31;
    int m = (idx >> 5) % M3;
    int b = idx / (M3 * CQ);
    int md = m / 144, mh = (m / 12) % 12, mw = m % 12;

    float gmax = -INFINITY, hmax = -INFINITY;
#pragma unroll
    for (int dd = 0; dd < 2; dd++)
#pragma unroll
        for (int dh = 0; dh < 2; dh++)
#pragma unroll
            for (int dw = 0; dw < 2; dw++) {
                int n = (2*md + dd) * 576 + (2*mh + dh) * 24 + (2*mw + dw);
                size_t o = ((size_t)b * N3 + n) * CQ + c;
                gmax = fmaxf(gmax, g_graw[o]);
                hmax = fmaxf(hmax, g_hraw[o]);
            }
    size_t po = ((size_t)b * M3 + m) * CQ + c;
    g_gp[po] = gmax;
    g_hp[po] = hmax;
}

// ---------------------------------------------------------------------------
// Attention + Wv epilogue + residual. Block = 128 threads = 128 queries.
// FFMA2 everywhere; no-max softmax (scores bounded ~|45| << 88 overflow).
// ---------------------------------------------------------------------------
__global__ __launch_bounds__(128) void attn_kernel(
    const float* __restrict__ x,
    const float* __restrict__ Wv,
    const float* __restrict__ gamma_p,
    float* __restrict__ out)
{
    __shared__ float sWv[CIN * CQ];  // 32 KB
    __shared__ float gk[TK][CQ];     // 6 KB
    __shared__ float hk[TK][CQ];     // 6 KB

    const int b   = blockIdx.y;
    const int tid = threadIdx.x;
    const int q   = blockIdx.x * 128 + tid;

    for (int i = tid; i < CIN * CQ; i += 128) sWv[i] = Wv[i];

    u64 fq2[16];
    {
        const ulonglong2* fb = (const ulonglong2*)(g_f + ((size_t)b * N3 + q) * CQ);
#pragma unroll
        for (int c = 0; c < 8; c++) {
            ulonglong2 v = fb[c];
            fq2[2*c] = v.x; fq2[2*c + 1] = v.y;
        }
    }

    u64 acc2[16];
#pragma unroll
    for (int i = 0; i < 16; i++) acc2[i] = 0ull;
    float l = 0.f;

    for (int k0 = 0; k0 < M3; k0 += TK) {
        __syncthreads();
        {
            const float4* gsrc = (const float4*)(g_gp + ((size_t)b * M3 + k0) * CQ);
            const float4* hsrc = (const float4*)(g_hp + ((size_t)b * M3 + k0) * CQ);
            float4* gdst = (float4*)&gk[0][0];
            float4* hdst = (float4*)&hk[0][0];
#pragma unroll
            for (int i = 0; i < (TK * CQ / 4) / 128; i++) {
                gdst[tid + i * 128] = gsrc[tid + i * 128];
                hdst[tid + i * 128] = hsrc[tid + i * 128];
            }
        }
        __syncthreads();

#pragma unroll 2
        for (int j = 0; j < TK; j++) {
            const ulonglong2* gp = (const ulonglong2*)&gk[j][0];
            u64 sa = 0ull, sb = 0ull;
#pragma unroll
            for (int c = 0; c < 8; c++) {
                ulonglong2 gv = gp[c];
                sa = fma2(fq2[2*c + 0], gv.x, sa);
                sb = fma2(fq2[2*c + 1], gv.y, sb);
            }
            float a0, a1, b0, b1;
            unpack2(sa, a0, a1);
            unpack2(sb, b0, b1);
            float s = (a0 + a1) + (b0 + b1);
            float p = __expf(s);
            l += p;
            u64 pp = pack2(p, p);
            const ulonglong2* hp = (const ulonglong2*)&hk[j][0];
#pragma unroll
            for (int c = 0; c < 8; c++) {
                ulonglong2 hv = hp[c];
                acc2[2*c + 0] = fma2(pp, hv.x, acc2[2*c + 0]);
                acc2[2*c + 1] = fma2(pp, hv.y, acc2[2*c + 1]);
            }
        }
    }

    {
        float inv = 1.0f / l;
        u64 iv = pack2(inv, inv);
#pragma unroll
        for (int i = 0; i < 16; i++) acc2[i] = mul2(acc2[i], iv);
    }

    const float gma = *gamma_p;
    size_t xb = (size_t)b * CIN * N3 + q;
#pragma unroll 4
    for (int cc = 0; cc < CIN; cc++) {
        const ulonglong2* wp = (const ulonglong2*)&sWv[cc * CQ];
        u64 ea = 0ull, eb = 0ull;
#pragma unroll
        for (int c = 0; c < 8; c++) {
            ulonglong2 w = wp[c];
            ea = fma2(acc2[2*c + 0], w.x, ea);
            eb = fma2(acc2[2*c + 1], w.y, eb);
        }
        float a0, a1, b0, b1;
        unpack2(ea, a0, a1);
        unpack2(eb, b0, b1);
        float s = (a0 + a1) + (b0 + b1);
        size_t o = xb + (size_t)cc * N3;
        out[o] = fmaf(gma, s, x[o]);
    }
}

// ---------------------------------------------------------------------------
extern "C" void kernel_launch(void* const* d_in, const int* in_sizes, int n_in,
                              void* d_out, int out_size)
{
    const float* x     = (const float*)d_in[0];
    const float* Wf    = (const float*)d_in[1];
    const float* Wg    = (const float*)d_in[2];
    const float* Wh    = (const float*)d_in[3];
    const float* Wv    = (const float*)d_in[4];
    const float* gamma = (const float*)d_in[5];
    float* out = (float*)d_out;

    dim3 pgrid(N3 / 256, B_, 3);
    proj_kernel<<<pgrid, 128>>>(x, Wf, Wg, Wh);

    int ptotal = B_ * M3 * CQ;
    pool_kernel<<<(ptotal + 255) / 256, 256>>>();

    dim3 agrid(N3 / 128, B_);
    attn_kernel<<<agrid, 128>>>(x, Wv, gamma, out);
}